// round 10
// baseline (speedup 1.0000x reference)
#include <cuda_runtime.h>
#include <cstdint>

// ---------------------------------------------------------------------------
// Flow net R8: 4pos x 4outch per thread, 4 blocks/SM (32 warps/SM), cp.async
// double-buffer, fused BN stats, channel-parallel fusion, paired flow head.
// ---------------------------------------------------------------------------

#define EPSV   1e-5f
#define SLOPEV 0.01f

// scratch layout (floats)
#define OFF_F0R    0u          // raw enc0 out      8*64*8192  = 4194304
#define OFF_T0     4194304u    // bn(f0)
#define OFF_F1R    8388608u    // raw enc1 out      8*128*4096 = 4194304
#define OFF_T1     12582912u   // bn(f1)
#define OFF_F2R    16777216u   // raw enc2 out      8*256*2048 = 4194304
#define OFF_FEATUP 20971520u   // fusion out, upsampled  8*11*4096 = 360448
#define OFF_D1R    21331968u   // raw dec1 out      4194304
#define OFF_D1UP   25526272u   // bn(d1) upsampled  8*128*8192 = 8388608
#define OFF_D0R    33914880u   // raw dec0 out      8388608
#define OFF_FL     42303488u   // flow raw          262144
#define OFF_SUM    42565632u   // 706
#define OFF_SQS    42566338u   // 706
#define SCRATCH_TOTAL 42567044u

__device__ float g_scratch[SCRATCH_TOTAL];

typedef unsigned long long u64t;

#define FMA2(acc, x, w) \
    asm("fma.rn.f32x2 %0, %1, %2, %0;" : "+l"(acc) : "l"(x), "l"(w))
#define PACK2(out, lo, hi) \
    asm("mov.b64 %0, {%1, %2};" : "=l"(out) : "f"(lo), "f"(hi))
#define UNPACK2(lo, hi, in) \
    asm("mov.b64 {%0, %1}, %2;" : "=f"(lo), "=f"(hi) : "l"(in))

__device__ __forceinline__ float bnl(float r, float sc, float sh) {
    float a = sc * r + sh;
    return a >= 0.f ? a : SLOPEV * a;
}

__device__ __forceinline__ void cp16(unsigned dst, const float* src, int bytes) {
    asm volatile("cp.async.ca.shared.global [%0], [%1], 16, %2;"
                 :: "r"(dst), "l"(src), "r"(bytes));
}

// ---------------------------------------------------------------------------
__global__ void zero_kernel(float* p, int n) {
    int i = blockIdx.x * 256 + threadIdx.x;
    if (i < n) p[i] = 0.f;
}

// ---------------------------------------------------------------------------
// K=3 conv, cp.async double-buffered. 256 threads -> 1024 positions x 4 outch.
// Each thread: 4 consecutive positions x 4 out channels (8 u64 f32x2 accs).
// src1/src2 full-resolution, pre-transformed. Pure-copy staging.
// Epilogue: bias + store raw + fused BN-stat partial reduction.
// ---------------------------------------------------------------------------
template<int STRIDE, int CT>
__global__ __launch_bounds__(256, 4)
void conv3_cp(const float* __restrict__ src1, int C1,
              const float* __restrict__ src2, int C2,
              int Lin, int Lout, int Cin, int CinPad,
              const float* __restrict__ w, const float* __restrict__ bias,
              float* __restrict__ y,
              float* __restrict__ gsum, float* __restrict__ gsqs)
{
    constexpr int TP = 1024;
    constexpr int TW = TP * STRIDE + 8;
    constexpr int NV = TW / 4;
    constexpr int XN = 4 * STRIDE + 5;   // 9 (s1) / 13 (s2)

    extern __shared__ float sh[];
    __shared__ float redS[4], redQ[4];

    const int tid = threadIdx.x;
    const int P0  = blockIdx.x * TP;
    const int co0 = blockIdx.y * 4;
    const int b   = blockIdx.z;
    const int hs  = P0 * STRIDE - 4;
    const int wsN = CinPad * 12;
    float* ws = sh;
    float* xs = sh + wsN;

    if (tid < 4) { redS[tid] = 0.f; redQ[tid] = 0.f; }

    // stage ALL weights once: ws[ci*12 + k*4 + u] = w[co0+u][ci][k]
    for (int idx = tid; idx < wsN; idx += 256) {
        int ci = idx / 12;
        int r  = idx - ci * 12;
        int k  = r >> 2, u = r & 3;
        ws[idx] = (ci < Cin) ? w[((size_t)(co0 + u) * Cin + ci) * 3 + k] : 0.f;
    }

    u64t acc[4][2];
    #pragma unroll
    for (int j = 0; j < 4; j++) {
        acc[j][0] = 0ull; acc[j][1] = 0ull;
    }

    const int ntile = CinPad / CT;

    auto stage = [&](int t, int buf) {
        float* xb = xs + buf * (CT * TW);
        int ci0 = t * CT;
        #pragma unroll
        for (int ci = 0; ci < CT; ci++) {
            int cg = ci0 + ci;
            bool cv = (cg < Cin);
            const float* row;
            if (cg < C1)      row = src1 + (size_t)(b * C1 + cg) * Lin;
            else if (cv)      row = src2 + (size_t)(b * C2 + (cg - C1)) * Lin;
            else              row = src1;
            unsigned sb = (unsigned)__cvta_generic_to_shared(xb + ci * TW);
            for (int v = tid; v < NV; v += 256) {
                int p   = hs + v * 4;
                int okb = (cv && p >= 0 && p < Lin) ? 16 : 0;
                int pc  = min(max(p, 0), Lin - 4);
                cp16(sb + v * 16, row + pc, okb);
            }
        }
    };

    stage(0, 0);
    asm volatile("cp.async.commit_group;");

    for (int t = 0; t < ntile; t++) {
        asm volatile("cp.async.wait_group 0;");
        __syncthreads();
        if (t + 1 < ntile) {
            stage(t + 1, (t + 1) & 1);
            asm volatile("cp.async.commit_group;");
        }
        const float* xbc = xs + (t & 1) * (CT * TW);
        #pragma unroll
        for (int ci = 0; ci < CT; ci++) {
            int gci = t * CT + ci;
            const float* xr = xbc + ci * TW + tid * 4 * STRIDE;
            float xv[XN];
            {
                float4 a0 = *(const float4*)xr;
                float4 a1 = *(const float4*)(xr + 4);
                xv[0] = a0.x; xv[1] = a0.y; xv[2] = a0.z; xv[3] = a0.w;
                xv[4] = a1.x; xv[5] = a1.y; xv[6] = a1.z; xv[7] = a1.w;
                if (STRIDE == 1) {
                    xv[8] = xr[8];
                } else {
                    float4 a2 = *(const float4*)(xr + 8);
                    xv[8] = a2.x; xv[9] = a2.y; xv[10] = a2.z; xv[11] = a2.w;
                    xv[12] = 0.f;
                }
            }
            const u64t* wrow = (const u64t*)(ws + gci * 12);
            #pragma unroll
            for (int k = 0; k < 3; k++) {
                u64t w0 = wrow[k * 2 + 0], w1 = wrow[k * 2 + 1];
                #pragma unroll
                for (int j = 0; j < 4; j++) {
                    float xsc = xv[j * STRIDE + k + 3];
                    u64t xq;
                    PACK2(xq, xsc, xsc);
                    FMA2(acc[j][0], xq, w0);
                    FMA2(acc[j][1], xq, w1);
                }
            }
        }
    }

    // epilogue: bias + raw store + fused BN-stat reduction
    const int lid = tid & 31;
    #pragma unroll
    for (int u = 0; u < 2; u++) {
        float o0[4], o1[4];
        #pragma unroll
        for (int j = 0; j < 4; j++) UNPACK2(o0[j], o1[j], acc[j][u]);
        int c0 = co0 + 2 * u;
        float b0 = bias[c0], b1 = bias[c0 + 1];
        float s0 = 0.f, q0 = 0.f, s1 = 0.f, q1 = 0.f;
        #pragma unroll
        for (int j = 0; j < 4; j++) {
            o0[j] += b0; o1[j] += b1;
            s0 += o0[j]; q0 += o0[j] * o0[j];
            s1 += o1[j]; q1 += o1[j] * o1[j];
        }
        *(float4*)&y[((size_t)(b * (gridDim.y * 4) + c0)) * Lout + P0 + tid * 4] =
            make_float4(o0[0], o0[1], o0[2], o0[3]);
        *(float4*)&y[((size_t)(b * (gridDim.y * 4) + c0 + 1)) * Lout + P0 + tid * 4] =
            make_float4(o1[0], o1[1], o1[2], o1[3]);
        unsigned full = 0xffffffffu;
        #pragma unroll
        for (int o = 16; o > 0; o >>= 1) {
            s0 += __shfl_down_sync(full, s0, o);
            q0 += __shfl_down_sync(full, q0, o);
            s1 += __shfl_down_sync(full, s1, o);
            q1 += __shfl_down_sync(full, q1, o);
        }
        if (lid == 0) {
            atomicAdd(&redS[2 * u], s0);     atomicAdd(&redQ[2 * u], q0);
            atomicAdd(&redS[2 * u + 1], s1); atomicAdd(&redQ[2 * u + 1], q1);
        }
    }
    __syncthreads();
    if (tid < 4) {
        atomicAdd(&gsum[co0 + tid], redS[tid]);
        atomicAdd(&gsqs[co0 + tid], redQ[tid]);
    }
}

// ---------------------------------------------------------------------------
// BN apply -> separate output (same resolution)
// ---------------------------------------------------------------------------
__global__ __launch_bounds__(256)
void bn_out_kernel(const float* __restrict__ raw, float* __restrict__ out,
                   int C, int L,
                   const float* __restrict__ ssum, const float* __restrict__ sqs,
                   const float* __restrict__ g, const float* __restrict__ be,
                   float invn)
{
    size_t i4 = (size_t)blockIdx.x * 256 + threadIdx.x;
    int c = (int)((i4 * 4) / (size_t)L) % C;
    float m   = ssum[c] * invn;
    float var = sqs[c] * invn - m * m;
    float sc  = g[c] * rsqrtf(var + EPSV);
    float sh  = be[c] - sc * m;
    float4 v = ((const float4*)raw)[i4];
    float4 o;
    o.x = bnl(v.x, sc, sh); o.y = bnl(v.y, sc, sh);
    o.z = bnl(v.z, sc, sh); o.w = bnl(v.w, sc, sh);
    ((float4*)out)[i4] = o;
}

// ---------------------------------------------------------------------------
// BN apply + nearest-upsample x2 -> separate output (double resolution)
// ---------------------------------------------------------------------------
__global__ __launch_bounds__(256)
void bn_up2_kernel(const float* __restrict__ raw, float* __restrict__ out,
                   int C, int Lin,
                   const float* __restrict__ ssum, const float* __restrict__ sqs,
                   const float* __restrict__ g, const float* __restrict__ be,
                   float invn)
{
    size_t i2 = (size_t)blockIdx.x * 256 + threadIdx.x;   // over B*C*Lin/2
    int c = (int)((i2 * 2) / (size_t)Lin) % C;
    float m   = ssum[c] * invn;
    float var = sqs[c] * invn - m * m;
    float sc  = g[c] * rsqrtf(var + EPSV);
    float sh  = be[c] - sc * m;
    float2 v = ((const float2*)raw)[i2];
    float a = bnl(v.x, sc, sh);
    float d = bnl(v.y, sc, sh);
    ((float4*)out)[i2] = make_float4(a, a, d, d);
}

// ---------------------------------------------------------------------------
// BN batch-stat reduce (flow head only, C=2)
// ---------------------------------------------------------------------------
__global__ __launch_bounds__(256)
void reduce_kernel(const float* __restrict__ y, int C, int L,
                   float* __restrict__ s_out, float* __restrict__ q_out)
{
    int c = blockIdx.x, b = blockIdx.y;
    const float* p = y + ((size_t)(b * C + c)) * L;
    float s = 0.f, q = 0.f;
    for (int i = threadIdx.x * 4; i < L; i += 1024) {
        float4 v = *(const float4*)(p + i);
        s += v.x + v.y + v.z + v.w;
        q += v.x * v.x + v.y * v.y + v.z * v.z + v.w * v.w;
    }
    unsigned full = 0xffffffffu;
    #pragma unroll
    for (int o = 16; o > 0; o >>= 1) {
        s += __shfl_down_sync(full, s, o);
        q += __shfl_down_sync(full, q, o);
    }
    __shared__ float shs[8], shq[8];
    int wid = threadIdx.x >> 5, lid = threadIdx.x & 31;
    if (lid == 0) { shs[wid] = s; shq[wid] = q; }
    __syncthreads();
    if (threadIdx.x == 0) {
        float ts = 0.f, tq = 0.f;
        #pragma unroll
        for (int i = 0; i < 8; i++) { ts += shs[i]; tq += shq[i]; }
        atomicAdd(&s_out[c], ts);
        atomicAdd(&q_out[c], tq);
    }
}

// ---------------------------------------------------------------------------
// Fusion: banded correlation, K=3 patch, D=5, on raw enc2 output with BN
// fused into staging. Channel-split over blockIdx.z (64 ch each), partial
// results atomically accumulated into pre-zeroed featup (B, 11, 4096),
// written duplicated (pre-upsampled).
// ---------------------------------------------------------------------------
__global__ __launch_bounds__(128)
void fusion_kernel(const float* __restrict__ f2r, float* __restrict__ featup,
                   const float* __restrict__ ssum, const float* __restrict__ sqs,
                   const float* __restrict__ gamma, const float* __restrict__ beta,
                   float invn)
{
    const int Nn = 2048, C = 256;
    const int b   = blockIdx.y;
    const int i0  = blockIdx.x * 128;
    const int cb  = blockIdx.z * 64;      // channel chunk base
    const int tid = threadIdx.x;
    const int i   = i0 + tid;
    __shared__ float tile[16][144];
    __shared__ float csc[64], csh[64];

    if (tid < 64) {
        int c = cb + tid;
        float m = ssum[c] * invn;
        float var = sqs[c] * invn - m * m;
        float sc = gamma[c] * rsqrtf(var + EPSV);
        csc[tid] = sc;
        csh[tid] = beta[c] - sc * m;
    }

    float acc[11];
    #pragma unroll
    for (int d = 0; d < 11; d++) acc[d] = 0.f;

    const bool interior = (i >= 5) && (i <= Nn - 6);

    for (int c0 = 0; c0 < 64; c0 += 16) {
        __syncthreads();
        for (int idx = tid; idx < 16 * 140; idx += 128) {
            int c = idx / 140, off = idx - c * 140;
            int p = i0 - 6 + off;
            p = min(max(p, 0), Nn - 1);
            float r = f2r[((size_t)(b * C + cb + c0 + c)) * Nn + p];
            tile[c][off] = bnl(r, csc[c0 + c], csh[c0 + c]);
        }
        __syncthreads();
        for (int c = 0; c < 16; c++) {
            float v[13];
            #pragma unroll
            for (int m = 0; m < 13; m++) v[m] = tile[c][tid + m];
            float A0 = v[5], A1 = v[6], A2 = v[7];
            if (interior) {
                #pragma unroll
                for (int dd = 0; dd < 11; dd++)
                    acc[dd] += A0 * v[dd] + A1 * v[dd + 1] + A2 * v[dd + 2];
            } else {
                for (int dd = 0; dd < 11; dd++) {
                    int j = i + dd - 5;
                    j = min(max(j, 0), Nn - 1);
                    int o0 = max(j - 1, 0) - i0 + 6;
                    int o1 = j - i0 + 6;
                    int o2 = min(j + 1, Nn - 1) - i0 + 6;
                    acc[dd] += A0 * tile[c][o0] + A1 * tile[c][o1] + A2 * tile[c][o2];
                }
            }
        }
    }
    #pragma unroll
    for (int dd = 0; dd < 11; dd++) {
        float* fo = &featup[((size_t)(b * 11 + dd)) * 4096 + 2 * i];
        atomicAdd(fo, acc[dd]);
        atomicAdd(fo + 1, acc[dd]);
    }
}

// ---------------------------------------------------------------------------
// Flow head: K=1 conv over concat(x1 raw, up(bn(d0))). One thread computes
// the upsample-twin positions (2i, 2i+1) sharing all d0 loads.
// ---------------------------------------------------------------------------
__global__ __launch_bounds__(256)
void flow_conv_kernel(const float* __restrict__ x1, const float* __restrict__ d0,
                      const float* __restrict__ w, const float* __restrict__ bias,
                      const float* __restrict__ ssum, const float* __restrict__ sqs,
                      const float* __restrict__ gamma, const float* __restrict__ beta,
                      float invn,
                      float* __restrict__ out)
{
    const int Nn = 16384;
    __shared__ float csc[128], csh[128];
    int tid = threadIdx.x;
    if (tid < 128) {
        float m = ssum[tid] * invn;
        float var = sqs[tid] * invn - m * m;
        float sc = gamma[tid] * rsqrtf(var + EPSV);
        csc[tid] = sc;
        csh[tid] = beta[tid] - sc * m;
    }
    __syncthreads();

    int b = blockIdx.y;
    int i = blockIdx.x * 256 + tid;          // 0..8191
    float2 xv = ((const float2*)&x1[(size_t)b * Nn])[i];
    float a00 = w[0] * xv.x, a01 = w[0] * xv.y;
    float a10 = w[129] * xv.x, a11 = w[129] * xv.y;
    const float* dp = d0 + (size_t)b * 128 * 8192 + i;
    #pragma unroll 4
    for (int ci = 0; ci < 128; ci++) {
        float r = dp[(size_t)ci * 8192];
        float v = bnl(r, csc[ci], csh[ci]);
        a00 += w[1 + ci] * v;   a01 += w[1 + ci] * v;
        a10 += w[130 + ci] * v; a11 += w[130 + ci] * v;
    }
    ((float2*)&out[((size_t)(b * 2 + 0)) * Nn])[i] = make_float2(a00 + bias[0], a01 + bias[0]);
    ((float2*)&out[((size_t)(b * 2 + 1)) * Nn])[i] = make_float2(a10 + bias[1], a11 + bias[1]);
}

// ---------------------------------------------------------------------------
// Flow BN apply + LeakyReLU + transpose to (B, N, 2)
// ---------------------------------------------------------------------------
__global__ __launch_bounds__(256)
void flow_apply_kernel(const float* __restrict__ fl,
                       const float* __restrict__ ssum, const float* __restrict__ sqs,
                       const float* __restrict__ gamma, const float* __restrict__ beta,
                       float* __restrict__ out, float invn)
{
    const int Nn = 16384;
    int b = blockIdx.y;
    int p = blockIdx.x * 256 + threadIdx.x;
    float m0 = ssum[0] * invn, m1 = ssum[1] * invn;
    float v0 = sqs[0] * invn - m0 * m0;
    float v1 = sqs[1] * invn - m1 * m1;
    float sc0 = gamma[0] * rsqrtf(v0 + EPSV), sh0 = beta[0] - sc0 * m0;
    float sc1 = gamma[1] * rsqrtf(v1 + EPSV), sh1 = beta[1] - sc1 * m1;
    float a = fl[((size_t)(b * 2 + 0)) * Nn + p];
    float c = fl[((size_t)(b * 2 + 1)) * Nn + p];
    float2 r;
    r.x = bnl(a, sc0, sh0);
    r.y = bnl(c, sc1, sh1);
    ((float2*)out)[(size_t)b * Nn + p] = r;
}

// ---------------------------------------------------------------------------
extern "C" void kernel_launch(void* const* d_in, const int* in_sizes, int n_in,
                              void* d_out, int out_size)
{
    (void)in_sizes; (void)n_in; (void)out_size;
    const float* scan1 = (const float*)d_in[0];
    const float* e0w = (const float*)d_in[1];
    const float* e0b = (const float*)d_in[2];
    const float* e0g = (const float*)d_in[3];
    const float* e0e = (const float*)d_in[4];
    const float* e1w = (const float*)d_in[5];
    const float* e1b = (const float*)d_in[6];
    const float* e1g = (const float*)d_in[7];
    const float* e1e = (const float*)d_in[8];
    const float* e2w = (const float*)d_in[9];
    const float* e2b = (const float*)d_in[10];
    const float* e2g = (const float*)d_in[11];
    const float* e2e = (const float*)d_in[12];
    const float* d1w = (const float*)d_in[13];
    const float* d1b = (const float*)d_in[14];
    const float* d1g = (const float*)d_in[15];
    const float* d1e = (const float*)d_in[16];
    const float* d0w = (const float*)d_in[17];
    const float* d0b = (const float*)d_in[18];
    const float* d0g = (const float*)d_in[19];
    const float* d0e = (const float*)d_in[20];
    const float* fw  = (const float*)d_in[21];
    const float* fb  = (const float*)d_in[22];
    const float* fg  = (const float*)d_in[23];
    const float* fe  = (const float*)d_in[24];

    float* base = nullptr;
    cudaGetSymbolAddress((void**)&base, g_scratch);
    float* f0r    = base + OFF_F0R;
    float* t0     = base + OFF_T0;
    float* f1r    = base + OFF_F1R;
    float* t1     = base + OFF_T1;
    float* f2r    = base + OFF_F2R;
    float* featup = base + OFF_FEATUP;
    float* d1r    = base + OFF_D1R;
    float* d1up   = base + OFF_D1UP;
    float* d0r    = base + OFF_D0R;
    float* fl     = base + OFF_FL;
    float* sum    = base + OFF_SUM;
    float* sqs    = base + OFF_SQS;

    const float i0n = 1.f / (8.f * 8192.f);
    const float i1n = 1.f / (8.f * 4096.f);
    const float i2n = 1.f / (8.f * 2048.f);

    // dynamic smem sizes (bytes): CinPad*12*4 + 2*CT*TW*4
    const int SM_E0 = (1 * 12 + 2 * 1 * 2056) * 4;     // 16496
    const int SM_E1 = (64 * 12 + 2 * 2 * 2056) * 4;    // 35968
    const int SM_E2 = (128 * 12 + 2 * 2 * 2056) * 4;   // 39040
    const int SM_D1 = (140 * 12 + 2 * 4 * 1032) * 4;   // 39744
    const int SM_D0 = (192 * 12 + 2 * 4 * 1032) * 4;   // 42240
    cudaFuncSetAttribute(conv3_cp<2, 1>, cudaFuncAttributeMaxDynamicSharedMemorySize, SM_E0);
    cudaFuncSetAttribute(conv3_cp<2, 2>, cudaFuncAttributeMaxDynamicSharedMemorySize, SM_E2);
    cudaFuncSetAttribute(conv3_cp<1, 4>, cudaFuncAttributeMaxDynamicSharedMemorySize, SM_D0);

    zero_kernel<<<6, 256>>>(sum, 1412);
    zero_kernel<<<1408, 256>>>(featup, 360448);

    // enc0: scan1 (B,1,16384) -> f0r (B,64,8192)
    conv3_cp<2, 1><<<dim3(8, 16, 8), 256, SM_E0>>>(
        scan1, 1, nullptr, 0, 16384, 8192, 1, 1,
        e0w, e0b, f0r, sum + 0, sqs + 0);
    bn_out_kernel<<<4096, 256>>>(f0r, t0, 64, 8192, sum + 0, sqs + 0, e0g, e0e, i0n);

    // enc1: t0 -> f1r (B,128,4096)
    conv3_cp<2, 2><<<dim3(4, 32, 8), 256, SM_E1>>>(
        t0, 64, nullptr, 0, 8192, 4096, 64, 64,
        e1w, e1b, f1r, sum + 64, sqs + 64);
    bn_out_kernel<<<4096, 256>>>(f1r, t1, 128, 4096, sum + 64, sqs + 64, e1g, e1e, i1n);

    // enc2: t1 -> f2r (B,256,2048)
    conv3_cp<2, 2><<<dim3(2, 64, 8), 256, SM_E2>>>(
        t1, 128, nullptr, 0, 4096, 2048, 128, 128,
        e2w, e2b, f2r, sum + 192, sqs + 192);

    // fusion on bn(f2r) -> featup (B,11,4096), pre-upsampled, channel-split
    fusion_kernel<<<dim3(16, 8, 4), 128>>>(f2r, featup,
                                           sum + 192, sqs + 192, e2g, e2e, i2n);

    // dec1: concat(t1[128], featup[11]) -> d1r (B,128,4096)
    conv3_cp<1, 4><<<dim3(4, 32, 8), 256, SM_D1>>>(
        t1, 128, featup, 11, 4096, 4096, 139, 140,
        d1w, d1b, d1r, sum + 448, sqs + 448);
    bn_up2_kernel<<<8192, 256>>>(d1r, d1up, 128, 4096, sum + 448, sqs + 448, d1g, d1e, i1n);

    // dec0: concat(t0[64], d1up[128]) -> d0r (B,128,8192)
    conv3_cp<1, 4><<<dim3(8, 32, 8), 256, SM_D0>>>(
        t0, 64, d1up, 128, 8192, 8192, 192, 192,
        d0w, d0b, d0r, sum + 576, sqs + 576);

    // flow head
    flow_conv_kernel<<<dim3(32, 8), 256>>>(scan1, d0r, fw, fb,
                                           sum + 576, sqs + 576, d0g, d0e, i0n, fl);
    reduce_kernel<<<dim3(2, 8), 256>>>(fl, 2, 16384, sum + 704, sqs + 704);
    flow_apply_kernel<<<dim3(64, 8), 256>>>(fl, sum + 704, sqs + 704, fg, fe,
                                            (float*)d_out, 1.f / (8.f * 16384.f));
}

// round 11
// speedup vs baseline: 2.0429x; 2.0429x over previous
#include <cuda_runtime.h>
#include <cstdint>

// ---------------------------------------------------------------------------
// Flow net R11: 4pos x 8outch per thread, LDS.128 weight loads + deduped
// x packs (issue-slot diet), cp.async double-buffer, fused BN stats,
// channel-parallel fusion, paired flow head.
// ---------------------------------------------------------------------------

#define EPSV   1e-5f
#define SLOPEV 0.01f

// scratch layout (floats)
#define OFF_F0R    0u          // raw enc0 out      8*64*8192  = 4194304
#define OFF_T0     4194304u    // bn(f0)
#define OFF_F1R    8388608u    // raw enc1 out      8*128*4096 = 4194304
#define OFF_T1     12582912u   // bn(f1)
#define OFF_F2R    16777216u   // raw enc2 out      8*256*2048 = 4194304
#define OFF_FEATUP 20971520u   // fusion out, upsampled  8*11*4096 = 360448
#define OFF_D1R    21331968u   // raw dec1 out      4194304
#define OFF_D1UP   25526272u   // bn(d1) upsampled  8*128*8192 = 8388608
#define OFF_D0R    33914880u   // raw dec0 out      8388608
#define OFF_FL     42303488u   // flow raw          262144
#define OFF_SUM    42565632u   // 706
#define OFF_SQS    42566338u   // 706
#define SCRATCH_TOTAL 42567044u

__device__ float g_scratch[SCRATCH_TOTAL];

typedef unsigned long long u64t;

#define FMA2(acc, x, w) \
    asm("fma.rn.f32x2 %0, %1, %2, %0;" : "+l"(acc) : "l"(x), "l"(w))
#define PACK2(out, lo, hi) \
    asm("mov.b64 %0, {%1, %2};" : "=l"(out) : "f"(lo), "f"(hi))
#define UNPACK2(lo, hi, in) \
    asm("mov.b64 {%0, %1}, %2;" : "=f"(lo), "=f"(hi) : "l"(in))

__device__ __forceinline__ float bnl(float r, float sc, float sh) {
    float a = sc * r + sh;
    return a >= 0.f ? a : SLOPEV * a;
}

__device__ __forceinline__ void cp16(unsigned dst, const float* src, int bytes) {
    asm volatile("cp.async.ca.shared.global [%0], [%1], 16, %2;"
                 :: "r"(dst), "l"(src), "r"(bytes));
}

// ---------------------------------------------------------------------------
__global__ void zero_kernel(float* p, int n) {
    int i = blockIdx.x * 256 + threadIdx.x;
    if (i < n) p[i] = 0.f;
}

// ---------------------------------------------------------------------------
// K=3 conv, cp.async double-buffered. 256 threads -> 1024 positions x 8 outch.
// Each thread: 4 consecutive positions x 8 out channels (16 u64 f32x2 accs).
// Weights loaded as LDS.128 (ulonglong2); x values pre-packed once (dedup).
// Epilogue: bias + store raw + fused BN-stat partial reduction.
// ---------------------------------------------------------------------------
template<int STRIDE, int CT>
__global__ __launch_bounds__(256, 3)
void conv3_cp(const float* __restrict__ src1, int C1,
              const float* __restrict__ src2, int C2,
              int Lin, int Lout, int Cin, int CinPad,
              const float* __restrict__ w, const float* __restrict__ bias,
              float* __restrict__ y,
              float* __restrict__ gsum, float* __restrict__ gsqs)
{
    constexpr int TP = 1024;
    constexpr int TW = TP * STRIDE + 8;
    constexpr int NV = TW / 4;
    constexpr int XN = 4 * STRIDE + 5;   // floats staged per thread
    constexpr int NQ = 3 * STRIDE + 3;   // distinct packed x values (6 / 9)

    extern __shared__ float sh[];
    __shared__ float redS[8], redQ[8];

    const int tid = threadIdx.x;
    const int P0  = blockIdx.x * TP;
    const int co0 = blockIdx.y * 8;
    const int b   = blockIdx.z;
    const int hs  = P0 * STRIDE - 4;
    const int wsN = CinPad * 24;
    float* ws = sh;
    float* xs = sh + wsN;

    if (tid < 8) { redS[tid] = 0.f; redQ[tid] = 0.f; }

    // stage ALL weights once: ws[ci*24 + k*8 + u] = w[co0+u][ci][k]
    for (int idx = tid; idx < wsN; idx += 256) {
        int ci = idx / 24;
        int r  = idx - ci * 24;
        int k  = r >> 3, u = r & 7;
        ws[idx] = (ci < Cin) ? w[((size_t)(co0 + u) * Cin + ci) * 3 + k] : 0.f;
    }

    u64t acc[4][4];
    #pragma unroll
    for (int j = 0; j < 4; j++)
        #pragma unroll
        for (int u = 0; u < 4; u++) acc[j][u] = 0ull;

    const int ntile = CinPad / CT;

    auto stage = [&](int t, int buf) {
        float* xb = xs + buf * (CT * TW);
        int ci0 = t * CT;
        #pragma unroll
        for (int ci = 0; ci < CT; ci++) {
            int cg = ci0 + ci;
            bool cv = (cg < Cin);
            const float* row;
            if (cg < C1)      row = src1 + (size_t)(b * C1 + cg) * Lin;
            else if (cv)      row = src2 + (size_t)(b * C2 + (cg - C1)) * Lin;
            else              row = src1;
            unsigned sb = (unsigned)__cvta_generic_to_shared(xb + ci * TW);
            for (int v = tid; v < NV; v += 256) {
                int p   = hs + v * 4;
                int okb = (cv && p >= 0 && p < Lin) ? 16 : 0;
                int pc  = min(max(p, 0), Lin - 4);
                cp16(sb + v * 16, row + pc, okb);
            }
        }
    };

    stage(0, 0);
    asm volatile("cp.async.commit_group;");

    for (int t = 0; t < ntile; t++) {
        asm volatile("cp.async.wait_group 0;");
        __syncthreads();
        if (t + 1 < ntile) {
            stage(t + 1, (t + 1) & 1);
            asm volatile("cp.async.commit_group;");
        }
        const float* xbc = xs + (t & 1) * (CT * TW);
        #pragma unroll
        for (int ci = 0; ci < CT; ci++) {
            int gci = t * CT + ci;
            const float* xr = xbc + ci * TW + tid * 4 * STRIDE;
            float xv[XN];
            {
                float4 a0 = *(const float4*)xr;
                float4 a1 = *(const float4*)(xr + 4);
                xv[0] = a0.x; xv[1] = a0.y; xv[2] = a0.z; xv[3] = a0.w;
                xv[4] = a1.x; xv[5] = a1.y; xv[6] = a1.z; xv[7] = a1.w;
                if (STRIDE == 1) {
                    xv[8] = xr[8];
                } else {
                    float4 a2 = *(const float4*)(xr + 8);
                    xv[8] = a2.x; xv[9] = a2.y; xv[10] = a2.z; xv[11] = a2.w;
                    xv[12] = 0.f;
                }
            }
            // dedup: pack each distinct x value once
            u64t xq[NQ];
            #pragma unroll
            for (int i = 0; i < NQ; i++) PACK2(xq[i], xv[i + 3], xv[i + 3]);

            const char* wbase = (const char*)(ws + gci * 24);
            #pragma unroll
            for (int k = 0; k < 3; k++) {
                ulonglong2 wa = *(const ulonglong2*)(wbase + k * 32);
                ulonglong2 wb = *(const ulonglong2*)(wbase + k * 32 + 16);
                #pragma unroll
                for (int j = 0; j < 4; j++) {
                    u64t xqv = xq[j * STRIDE + k];
                    FMA2(acc[j][0], xqv, wa.x);
                    FMA2(acc[j][1], xqv, wa.y);
                    FMA2(acc[j][2], xqv, wb.x);
                    FMA2(acc[j][3], xqv, wb.y);
                }
            }
        }
    }

    // epilogue: bias + raw store + fused BN-stat reduction
    const int lid = tid & 31;
    #pragma unroll
    for (int u = 0; u < 4; u++) {
        float o0[4], o1[4];
        #pragma unroll
        for (int j = 0; j < 4; j++) UNPACK2(o0[j], o1[j], acc[j][u]);
        int c0 = co0 + 2 * u;
        float b0 = bias[c0], b1 = bias[c0 + 1];
        float s0 = 0.f, q0 = 0.f, s1 = 0.f, q1 = 0.f;
        #pragma unroll
        for (int j = 0; j < 4; j++) {
            o0[j] += b0; o1[j] += b1;
            s0 += o0[j]; q0 += o0[j] * o0[j];
            s1 += o1[j]; q1 += o1[j] * o1[j];
        }
        *(float4*)&y[((size_t)(b * (gridDim.y * 8) + c0)) * Lout + P0 + tid * 4] =
            make_float4(o0[0], o0[1], o0[2], o0[3]);
        *(float4*)&y[((size_t)(b * (gridDim.y * 8) + c0 + 1)) * Lout + P0 + tid * 4] =
            make_float4(o1[0], o1[1], o1[2], o1[3]);
        unsigned full = 0xffffffffu;
        #pragma unroll
        for (int o = 16; o > 0; o >>= 1) {
            s0 += __shfl_down_sync(full, s0, o);
            q0 += __shfl_down_sync(full, q0, o);
            s1 += __shfl_down_sync(full, s1, o);
            q1 += __shfl_down_sync(full, q1, o);
        }
        if (lid == 0) {
            atomicAdd(&redS[2 * u], s0);     atomicAdd(&redQ[2 * u], q0);
            atomicAdd(&redS[2 * u + 1], s1); atomicAdd(&redQ[2 * u + 1], q1);
        }
    }
    __syncthreads();
    if (tid < 8) {
        atomicAdd(&gsum[co0 + tid], redS[tid]);
        atomicAdd(&gsqs[co0 + tid], redQ[tid]);
    }
}

// ---------------------------------------------------------------------------
// BN apply -> separate output (same resolution)
// ---------------------------------------------------------------------------
__global__ __launch_bounds__(256)
void bn_out_kernel(const float* __restrict__ raw, float* __restrict__ out,
                   int C, int L,
                   const float* __restrict__ ssum, const float* __restrict__ sqs,
                   const float* __restrict__ g, const float* __restrict__ be,
                   float invn)
{
    size_t i4 = (size_t)blockIdx.x * 256 + threadIdx.x;
    int c = (int)((i4 * 4) / (size_t)L) % C;
    float m   = ssum[c] * invn;
    float var = sqs[c] * invn - m * m;
    float sc  = g[c] * rsqrtf(var + EPSV);
    float sh  = be[c] - sc * m;
    float4 v = ((const float4*)raw)[i4];
    float4 o;
    o.x = bnl(v.x, sc, sh); o.y = bnl(v.y, sc, sh);
    o.z = bnl(v.z, sc, sh); o.w = bnl(v.w, sc, sh);
    ((float4*)out)[i4] = o;
}

// ---------------------------------------------------------------------------
// BN apply + nearest-upsample x2 -> separate output (double resolution)
// ---------------------------------------------------------------------------
__global__ __launch_bounds__(256)
void bn_up2_kernel(const float* __restrict__ raw, float* __restrict__ out,
                   int C, int Lin,
                   const float* __restrict__ ssum, const float* __restrict__ sqs,
                   const float* __restrict__ g, const float* __restrict__ be,
                   float invn)
{
    size_t i2 = (size_t)blockIdx.x * 256 + threadIdx.x;   // over B*C*Lin/2
    int c = (int)((i2 * 2) / (size_t)Lin) % C;
    float m   = ssum[c] * invn;
    float var = sqs[c] * invn - m * m;
    float sc  = g[c] * rsqrtf(var + EPSV);
    float sh  = be[c] - sc * m;
    float2 v = ((const float2*)raw)[i2];
    float a = bnl(v.x, sc, sh);
    float d = bnl(v.y, sc, sh);
    ((float4*)out)[i2] = make_float4(a, a, d, d);
}

// ---------------------------------------------------------------------------
// BN batch-stat reduce (flow head only, C=2)
// ---------------------------------------------------------------------------
__global__ __launch_bounds__(256)
void reduce_kernel(const float* __restrict__ y, int C, int L,
                   float* __restrict__ s_out, float* __restrict__ q_out)
{
    int c = blockIdx.x, b = blockIdx.y;
    const float* p = y + ((size_t)(b * C + c)) * L;
    float s = 0.f, q = 0.f;
    for (int i = threadIdx.x * 4; i < L; i += 1024) {
        float4 v = *(const float4*)(p + i);
        s += v.x + v.y + v.z + v.w;
        q += v.x * v.x + v.y * v.y + v.z * v.z + v.w * v.w;
    }
    unsigned full = 0xffffffffu;
    #pragma unroll
    for (int o = 16; o > 0; o >>= 1) {
        s += __shfl_down_sync(full, s, o);
        q += __shfl_down_sync(full, q, o);
    }
    __shared__ float shs[8], shq[8];
    int wid = threadIdx.x >> 5, lid = threadIdx.x & 31;
    if (lid == 0) { shs[wid] = s; shq[wid] = q; }
    __syncthreads();
    if (threadIdx.x == 0) {
        float ts = 0.f, tq = 0.f;
        #pragma unroll
        for (int i = 0; i < 8; i++) { ts += shs[i]; tq += shq[i]; }
        atomicAdd(&s_out[c], ts);
        atomicAdd(&q_out[c], tq);
    }
}

// ---------------------------------------------------------------------------
// Fusion: banded correlation, K=3 patch, D=5, on raw enc2 output with BN
// fused into staging. Channel-split over blockIdx.z (64 ch each), partial
// results atomically accumulated into pre-zeroed featup (B, 11, 4096),
// written duplicated (pre-upsampled).
// ---------------------------------------------------------------------------
__global__ __launch_bounds__(128)
void fusion_kernel(const float* __restrict__ f2r, float* __restrict__ featup,
                   const float* __restrict__ ssum, const float* __restrict__ sqs,
                   const float* __restrict__ gamma, const float* __restrict__ beta,
                   float invn)
{
    const int Nn = 2048, C = 256;
    const int b   = blockIdx.y;
    const int i0  = blockIdx.x * 128;
    const int cb  = blockIdx.z * 64;      // channel chunk base
    const int tid = threadIdx.x;
    const int i   = i0 + tid;
    __shared__ float tile[16][144];
    __shared__ float csc[64], csh[64];

    if (tid < 64) {
        int c = cb + tid;
        float m = ssum[c] * invn;
        float var = sqs[c] * invn - m * m;
        float sc = gamma[c] * rsqrtf(var + EPSV);
        csc[tid] = sc;
        csh[tid] = beta[c] - sc * m;
    }

    float acc[11];
    #pragma unroll
    for (int d = 0; d < 11; d++) acc[d] = 0.f;

    const bool interior = (i >= 5) && (i <= Nn - 6);

    for (int c0 = 0; c0 < 64; c0 += 16) {
        __syncthreads();
        for (int idx = tid; idx < 16 * 140; idx += 128) {
            int c = idx / 140, off = idx - c * 140;
            int p = i0 - 6 + off;
            p = min(max(p, 0), Nn - 1);
            float r = f2r[((size_t)(b * C + cb + c0 + c)) * Nn + p];
            tile[c][off] = bnl(r, csc[c0 + c], csh[c0 + c]);
        }
        __syncthreads();
        for (int c = 0; c < 16; c++) {
            float v[13];
            #pragma unroll
            for (int m = 0; m < 13; m++) v[m] = tile[c][tid + m];
            float A0 = v[5], A1 = v[6], A2 = v[7];
            if (interior) {
                #pragma unroll
                for (int dd = 0; dd < 11; dd++)
                    acc[dd] += A0 * v[dd] + A1 * v[dd + 1] + A2 * v[dd + 2];
            } else {
                for (int dd = 0; dd < 11; dd++) {
                    int j = i + dd - 5;
                    j = min(max(j, 0), Nn - 1);
                    int o0 = max(j - 1, 0) - i0 + 6;
                    int o1 = j - i0 + 6;
                    int o2 = min(j + 1, Nn - 1) - i0 + 6;
                    acc[dd] += A0 * tile[c][o0] + A1 * tile[c][o1] + A2 * tile[c][o2];
                }
            }
        }
    }
    #pragma unroll
    for (int dd = 0; dd < 11; dd++) {
        float* fo = &featup[((size_t)(b * 11 + dd)) * 4096 + 2 * i];
        atomicAdd(fo, acc[dd]);
        atomicAdd(fo + 1, acc[dd]);
    }
}

// ---------------------------------------------------------------------------
// Flow head: K=1 conv over concat(x1 raw, up(bn(d0))). One thread computes
// the upsample-twin positions (2i, 2i+1) sharing all d0 loads.
// ---------------------------------------------------------------------------
__global__ __launch_bounds__(256)
void flow_conv_kernel(const float* __restrict__ x1, const float* __restrict__ d0,
                      const float* __restrict__ w, const float* __restrict__ bias,
                      const float* __restrict__ ssum, const float* __restrict__ sqs,
                      const float* __restrict__ gamma, const float* __restrict__ beta,
                      float invn,
                      float* __restrict__ out)
{
    const int Nn = 16384;
    __shared__ float csc[128], csh[128];
    int tid = threadIdx.x;
    if (tid < 128) {
        float m = ssum[tid] * invn;
        float var = sqs[tid] * invn - m * m;
        float sc = gamma[tid] * rsqrtf(var + EPSV);
        csc[tid] = sc;
        csh[tid] = beta[tid] - sc * m;
    }
    __syncthreads();

    int b = blockIdx.y;
    int i = blockIdx.x * 256 + tid;          // 0..8191
    float2 xv = ((const float2*)&x1[(size_t)b * Nn])[i];
    float a00 = w[0] * xv.x, a01 = w[0] * xv.y;
    float a10 = w[129] * xv.x, a11 = w[129] * xv.y;
    const float* dp = d0 + (size_t)b * 128 * 8192 + i;
    #pragma unroll 4
    for (int ci = 0; ci < 128; ci++) {
        float r = dp[(size_t)ci * 8192];
        float v = bnl(r, csc[ci], csh[ci]);
        a00 += w[1 + ci] * v;   a01 += w[1 + ci] * v;
        a10 += w[130 + ci] * v; a11 += w[130 + ci] * v;
    }
    ((float2*)&out[((size_t)(b * 2 + 0)) * Nn])[i] = make_float2(a00 + bias[0], a01 + bias[0]);
    ((float2*)&out[((size_t)(b * 2 + 1)) * Nn])[i] = make_float2(a10 + bias[1], a11 + bias[1]);
}

// ---------------------------------------------------------------------------
// Flow BN apply + LeakyReLU + transpose to (B, N, 2)
// ---------------------------------------------------------------------------
__global__ __launch_bounds__(256)
void flow_apply_kernel(const float* __restrict__ fl,
                       const float* __restrict__ ssum, const float* __restrict__ sqs,
                       const float* __restrict__ gamma, const float* __restrict__ beta,
                       float* __restrict__ out, float invn)
{
    const int Nn = 16384;
    int b = blockIdx.y;
    int p = blockIdx.x * 256 + threadIdx.x;
    float m0 = ssum[0] * invn, m1 = ssum[1] * invn;
    float v0 = sqs[0] * invn - m0 * m0;
    float v1 = sqs[1] * invn - m1 * m1;
    float sc0 = gamma[0] * rsqrtf(v0 + EPSV), sh0 = beta[0] - sc0 * m0;
    float sc1 = gamma[1] * rsqrtf(v1 + EPSV), sh1 = beta[1] - sc1 * m1;
    float a = fl[((size_t)(b * 2 + 0)) * Nn + p];
    float c = fl[((size_t)(b * 2 + 1)) * Nn + p];
    float2 r;
    r.x = bnl(a, sc0, sh0);
    r.y = bnl(c, sc1, sh1);
    ((float2*)out)[(size_t)b * Nn + p] = r;
}

// ---------------------------------------------------------------------------
extern "C" void kernel_launch(void* const* d_in, const int* in_sizes, int n_in,
                              void* d_out, int out_size)
{
    (void)in_sizes; (void)n_in; (void)out_size;
    const float* scan1 = (const float*)d_in[0];
    const float* e0w = (const float*)d_in[1];
    const float* e0b = (const float*)d_in[2];
    const float* e0g = (const float*)d_in[3];
    const float* e0e = (const float*)d_in[4];
    const float* e1w = (const float*)d_in[5];
    const float* e1b = (const float*)d_in[6];
    const float* e1g = (const float*)d_in[7];
    const float* e1e = (const float*)d_in[8];
    const float* e2w = (const float*)d_in[9];
    const float* e2b = (const float*)d_in[10];
    const float* e2g = (const float*)d_in[11];
    const float* e2e = (const float*)d_in[12];
    const float* d1w = (const float*)d_in[13];
    const float* d1b = (const float*)d_in[14];
    const float* d1g = (const float*)d_in[15];
    const float* d1e = (const float*)d_in[16];
    const float* d0w = (const float*)d_in[17];
    const float* d0b = (const float*)d_in[18];
    const float* d0g = (const float*)d_in[19];
    const float* d0e = (const float*)d_in[20];
    const float* fw  = (const float*)d_in[21];
    const float* fb  = (const float*)d_in[22];
    const float* fg  = (const float*)d_in[23];
    const float* fe  = (const float*)d_in[24];

    float* base = nullptr;
    cudaGetSymbolAddress((void**)&base, g_scratch);
    float* f0r    = base + OFF_F0R;
    float* t0     = base + OFF_T0;
    float* f1r    = base + OFF_F1R;
    float* t1     = base + OFF_T1;
    float* f2r    = base + OFF_F2R;
    float* featup = base + OFF_FEATUP;
    float* d1r    = base + OFF_D1R;
    float* d1up   = base + OFF_D1UP;
    float* d0r    = base + OFF_D0R;
    float* fl     = base + OFF_FL;
    float* sum    = base + OFF_SUM;
    float* sqs    = base + OFF_SQS;

    const float i0n = 1.f / (8.f * 8192.f);
    const float i1n = 1.f / (8.f * 4096.f);
    const float i2n = 1.f / (8.f * 2048.f);

    // dynamic smem sizes (bytes): CinPad*24*4 + 2*CT*TW*4
    const int SM_E0 = (1 * 24 + 2 * 1 * 2056) * 4;     // 16544
    const int SM_E1 = (64 * 24 + 2 * 2 * 2056) * 4;    // 39040
    const int SM_E2 = (128 * 24 + 2 * 2 * 2056) * 4;   // 45184
    const int SM_D1 = (140 * 24 + 2 * 4 * 1032) * 4;   // 46464
    const int SM_D0 = (192 * 24 + 2 * 4 * 1032) * 4;   // 51456
    cudaFuncSetAttribute(conv3_cp<2, 1>, cudaFuncAttributeMaxDynamicSharedMemorySize, SM_E0);
    cudaFuncSetAttribute(conv3_cp<2, 2>, cudaFuncAttributeMaxDynamicSharedMemorySize, SM_E2);
    cudaFuncSetAttribute(conv3_cp<1, 4>, cudaFuncAttributeMaxDynamicSharedMemorySize, SM_D0);

    zero_kernel<<<6, 256>>>(sum, 1412);
    zero_kernel<<<1408, 256>>>(featup, 360448);

    // enc0: scan1 (B,1,16384) -> f0r (B,64,8192)
    conv3_cp<2, 1><<<dim3(8, 8, 8), 256, SM_E0>>>(
        scan1, 1, nullptr, 0, 16384, 8192, 1, 1,
        e0w, e0b, f0r, sum + 0, sqs + 0);
    bn_out_kernel<<<4096, 256>>>(f0r, t0, 64, 8192, sum + 0, sqs + 0, e0g, e0e, i0n);

    // enc1: t0 -> f1r (B,128,4096)
    conv3_cp<2, 2><<<dim3(4, 16, 8), 256, SM_E1>>>(
        t0, 64, nullptr, 0, 8192, 4096, 64, 64,
        e1w, e1b, f1r, sum + 64, sqs + 64);
    bn_out_kernel<<<4096, 256>>>(f1r, t1, 128, 4096, sum + 64, sqs + 64, e1g, e1e, i1n);

    // enc2: t1 -> f2r (B,256,2048)
    conv3_cp<2, 2><<<dim3(2, 32, 8), 256, SM_E2>>>(
        t1, 128, nullptr, 0, 4096, 2048, 128, 128,
        e2w, e2b, f2r, sum + 192, sqs + 192);

    // fusion on bn(f2r) -> featup (B,11,4096), pre-upsampled, channel-split
    fusion_kernel<<<dim3(16, 8, 4), 128>>>(f2r, featup,
                                           sum + 192, sqs + 192, e2g, e2e, i2n);

    // dec1: concat(t1[128], featup[11]) -> d1r (B,128,4096)
    conv3_cp<1, 4><<<dim3(4, 16, 8), 256, SM_D1>>>(
        t1, 128, featup, 11, 4096, 4096, 139, 140,
        d1w, d1b, d1r, sum + 448, sqs + 448);
    bn_up2_kernel<<<8192, 256>>>(d1r, d1up, 128, 4096, sum + 448, sqs + 448, d1g, d1e, i1n);

    // dec0: concat(t0[64], d1up[128]) -> d0r (B,128,8192)
    conv3_cp<1, 4><<<dim3(8, 16, 8), 256, SM_D0>>>(
        t0, 64, d1up, 128, 8192, 8192, 192, 192,
        d0w, d0b, d0r, sum + 576, sqs + 576);

    // flow head
    flow_conv_kernel<<<dim3(32, 8), 256>>>(scan1, d0r, fw, fb,
                                           sum + 576, sqs + 576, d0g, d0e, i0n, fl);
    reduce_kernel<<<dim3(2, 8), 256>>>(fl, 2, 16384, sum + 704, sqs + 704);
    flow_apply_kernel<<<dim3(64, 8), 256>>>(fl, sum + 704, sqs + 704, fg, fe,
                                            (float*)d_out, 1.f / (8.f * 16384.f));
}

// round 12
// speedup vs baseline: 2.2931x; 1.1224x over previous
#include <cuda_runtime.h>
#include <cstdint>

// ---------------------------------------------------------------------------
// Flow net R12: upsample-algebra convs (2-tap half-res src2 paths in dec1 and
// dec0), fused flow stats, R11's issue-dieted conv core for the encoders.
// ---------------------------------------------------------------------------

#define EPSV   1e-5f
#define SLOPEV 0.01f

// scratch layout (floats)
#define OFF_F0R    0u          // raw enc0 out      8*64*8192  = 4194304
#define OFF_T0     4194304u    // bn(f0)
#define OFF_F1R    8388608u    // raw enc1 out      8*128*4096 = 4194304
#define OFF_T1     12582912u   // bn(f1)
#define OFF_F2R    16777216u   // raw enc2 out      8*256*2048 = 4194304
#define OFF_FEAT   20971520u   // fusion out (half-res) 8*11*2048 = 180224
#define OFF_D1R    21151744u   // raw dec1 out      4194304
#define OFF_TD1    25346048u   // bn(d1) half-res   4194304
#define OFF_D0R    29540352u   // raw dec0 out      8388608
#define OFF_FL     37928960u   // flow raw          262144
#define OFF_SUM    38191104u   // 706
#define OFF_SQS    38191810u   // 706
#define SCRATCH_TOTAL 38192516u

__device__ float g_scratch[SCRATCH_TOTAL];

typedef unsigned long long u64t;

#define FMA2(acc, x, w) \
    asm("fma.rn.f32x2 %0, %1, %2, %0;" : "+l"(acc) : "l"(x), "l"(w))
#define PACK2(out, lo, hi) \
    asm("mov.b64 %0, {%1, %2};" : "=l"(out) : "f"(lo), "f"(hi))
#define UNPACK2(lo, hi, in) \
    asm("mov.b64 {%0, %1}, %2;" : "=f"(lo), "=f"(hi) : "l"(in))

__device__ __forceinline__ float bnl(float r, float sc, float sh) {
    float a = sc * r + sh;
    return a >= 0.f ? a : SLOPEV * a;
}

__device__ __forceinline__ void cp16(unsigned dst, const float* src, int bytes) {
    asm volatile("cp.async.ca.shared.global [%0], [%1], 16, %2;"
                 :: "r"(dst), "l"(src), "r"(bytes));
}

// ---------------------------------------------------------------------------
__global__ void zero_kernel(float* p, int n) {
    int i = blockIdx.x * 256 + threadIdx.x;
    if (i < n) p[i] = 0.f;
}

// ---------------------------------------------------------------------------
// Encoder K=3 conv (R11 core). 256 threads -> 1024 pos x 8 outch.
// ---------------------------------------------------------------------------
template<int STRIDE, int CT>
__global__ __launch_bounds__(256, 3)
void conv3_cp(const float* __restrict__ src1, int C1,
              int Lin, int Lout, int Cin, int CinPad,
              const float* __restrict__ w, const float* __restrict__ bias,
              float* __restrict__ y,
              float* __restrict__ gsum, float* __restrict__ gsqs)
{
    constexpr int TP = 1024;
    constexpr int TW = TP * STRIDE + 8;
    constexpr int NV = TW / 4;
    constexpr int XN = 4 * STRIDE + 5;
    constexpr int NQ = 3 * STRIDE + 3;

    extern __shared__ float sh[];
    __shared__ float redS[8], redQ[8];

    const int tid = threadIdx.x;
    const int P0  = blockIdx.x * TP;
    const int co0 = blockIdx.y * 8;
    const int b   = blockIdx.z;
    const int hs  = P0 * STRIDE - 4;
    const int wsN = CinPad * 24;
    float* ws = sh;
    float* xs = sh + wsN;

    if (tid < 8) { redS[tid] = 0.f; redQ[tid] = 0.f; }

    for (int idx = tid; idx < wsN; idx += 256) {
        int ci = idx / 24;
        int r  = idx - ci * 24;
        int k  = r >> 3, u = r & 7;
        ws[idx] = (ci < Cin) ? w[((size_t)(co0 + u) * Cin + ci) * 3 + k] : 0.f;
    }

    u64t acc[4][4];
    #pragma unroll
    for (int j = 0; j < 4; j++)
        #pragma unroll
        for (int u = 0; u < 4; u++) acc[j][u] = 0ull;

    const int ntile = CinPad / CT;

    auto stage = [&](int t, int buf) {
        float* xb = xs + buf * (CT * TW);
        int ci0 = t * CT;
        #pragma unroll
        for (int ci = 0; ci < CT; ci++) {
            int cg = ci0 + ci;
            bool cv = (cg < Cin);
            const float* row = src1 + (size_t)(b * C1 + (cv ? cg : 0)) * Lin;
            unsigned sb = (unsigned)__cvta_generic_to_shared(xb + ci * TW);
            for (int v = tid; v < NV; v += 256) {
                int p   = hs + v * 4;
                int okb = (cv && p >= 0 && p < Lin) ? 16 : 0;
                int pc  = min(max(p, 0), Lin - 4);
                cp16(sb + v * 16, row + pc, okb);
            }
        }
    };

    stage(0, 0);
    asm volatile("cp.async.commit_group;");

    for (int t = 0; t < ntile; t++) {
        asm volatile("cp.async.wait_group 0;");
        __syncthreads();
        if (t + 1 < ntile) {
            stage(t + 1, (t + 1) & 1);
            asm volatile("cp.async.commit_group;");
        }
        const float* xbc = xs + (t & 1) * (CT * TW);
        #pragma unroll
        for (int ci = 0; ci < CT; ci++) {
            int gci = t * CT + ci;
            const float* xr = xbc + ci * TW + tid * 4 * STRIDE;
            float xv[XN];
            {
                float4 a0 = *(const float4*)xr;
                float4 a1 = *(const float4*)(xr + 4);
                xv[0] = a0.x; xv[1] = a0.y; xv[2] = a0.z; xv[3] = a0.w;
                xv[4] = a1.x; xv[5] = a1.y; xv[6] = a1.z; xv[7] = a1.w;
                if (STRIDE == 1) {
                    xv[8] = xr[8];
                } else {
                    float4 a2 = *(const float4*)(xr + 8);
                    xv[8] = a2.x; xv[9] = a2.y; xv[10] = a2.z; xv[11] = a2.w;
                    xv[12] = 0.f;
                }
            }
            u64t xq[NQ];
            #pragma unroll
            for (int i = 0; i < NQ; i++) PACK2(xq[i], xv[i + 3], xv[i + 3]);

            const char* wbase = (const char*)(ws + gci * 24);
            #pragma unroll
            for (int k = 0; k < 3; k++) {
                ulonglong2 wa = *(const ulonglong2*)(wbase + k * 32);
                ulonglong2 wb = *(const ulonglong2*)(wbase + k * 32 + 16);
                #pragma unroll
                for (int j = 0; j < 4; j++) {
                    u64t xqv = xq[j * STRIDE + k];
                    FMA2(acc[j][0], xqv, wa.x);
                    FMA2(acc[j][1], xqv, wa.y);
                    FMA2(acc[j][2], xqv, wb.x);
                    FMA2(acc[j][3], xqv, wb.y);
                }
            }
        }
    }

    // epilogue
    const int lid = tid & 31;
    #pragma unroll
    for (int u = 0; u < 4; u++) {
        float o0[4], o1[4];
        #pragma unroll
        for (int j = 0; j < 4; j++) UNPACK2(o0[j], o1[j], acc[j][u]);
        int c0 = co0 + 2 * u;
        float b0 = bias[c0], b1 = bias[c0 + 1];
        float s0 = 0.f, q0 = 0.f, s1 = 0.f, q1 = 0.f;
        #pragma unroll
        for (int j = 0; j < 4; j++) {
            o0[j] += b0; o1[j] += b1;
            s0 += o0[j]; q0 += o0[j] * o0[j];
            s1 += o1[j]; q1 += o1[j] * o1[j];
        }
        *(float4*)&y[((size_t)(b * (gridDim.y * 8) + c0)) * Lout + P0 + tid * 4] =
            make_float4(o0[0], o0[1], o0[2], o0[3]);
        *(float4*)&y[((size_t)(b * (gridDim.y * 8) + c0 + 1)) * Lout + P0 + tid * 4] =
            make_float4(o1[0], o1[1], o1[2], o1[3]);
        unsigned full = 0xffffffffu;
        #pragma unroll
        for (int o = 16; o > 0; o >>= 1) {
            s0 += __shfl_down_sync(full, s0, o);
            q0 += __shfl_down_sync(full, q0, o);
            s1 += __shfl_down_sync(full, s1, o);
            q1 += __shfl_down_sync(full, q1, o);
        }
        if (lid == 0) {
            atomicAdd(&redS[2 * u], s0);     atomicAdd(&redQ[2 * u], q0);
            atomicAdd(&redS[2 * u + 1], s1); atomicAdd(&redQ[2 * u + 1], q1);
        }
    }
    __syncthreads();
    if (tid < 8) {
        atomicAdd(&gsum[co0 + tid], redS[tid]);
        atomicAdd(&gsqs[co0 + tid], redQ[tid]);
    }
}

// ---------------------------------------------------------------------------
// Decoder conv: src1 full-res (3-tap) + src2 HALF-res (2-tap via upsample
// algebra). Stride 1 only. 256 threads -> 1024 pos x 8 outch.
//   even p=2q: w0*x[q-1] + (w1+w2)*x[q]
//   odd  p=2q+1: (w0+w1)*x[q] + w2*x[q+1]
// ---------------------------------------------------------------------------
template<int CT>
__global__ __launch_bounds__(256, 3)
void conv3_mix(const float* __restrict__ src1, int C1,
               const float* __restrict__ src2, int C2, int C2Pad,
               int Lin, int Cout,
               const float* __restrict__ w, const float* __restrict__ bias,
               float* __restrict__ y,
               float* __restrict__ gsum, float* __restrict__ gsqs)
{
    constexpr int TP  = 1024;
    constexpr int TW1 = TP + 8;        // 1032
    constexpr int TW2 = TP / 2 + 8;    // 520
    constexpr int NV1 = TW1 / 4;
    constexpr int NV2 = TW2 / 4;

    extern __shared__ float sh[];
    __shared__ float redS[8], redQ[8];

    const int tid = threadIdx.x;
    const int P0  = blockIdx.x * TP;
    const int co0 = blockIdx.y * 8;
    const int b   = blockIdx.z;
    const int Lin2 = Lin >> 1;
    const int hs1 = P0 - 4;
    const int hs2 = P0 / 2 - 4;
    const int Cin = C1 + C2;

    const int ws3N = C1 * 24;
    const int ws2N = C2Pad * 32;
    float* ws3 = sh;
    float* ws2 = sh + ws3N;
    float* xs  = sh + ws3N + ws2N;

    if (tid < 8) { redS[tid] = 0.f; redQ[tid] = 0.f; }

    // weights: src1 channels (3-tap layout), src2 channels (4 combined sets)
    for (int idx = tid; idx < ws3N; idx += 256) {
        int ci = idx / 24;
        int r  = idx - ci * 24;
        int k  = r >> 3, u = r & 7;
        ws3[idx] = w[((size_t)(co0 + u) * Cin + ci) * 3 + k];
    }
    for (int idx = tid; idx < C2Pad * 8; idx += 256) {
        int ci2 = idx / 8;
        int u   = idx & 7;
        float w0 = 0.f, w1 = 0.f, w2 = 0.f;
        if (ci2 < C2) {
            const float* wp = &w[((size_t)(co0 + u) * Cin + C1 + ci2) * 3];
            w0 = wp[0]; w1 = wp[1]; w2 = wp[2];
        }
        float* base = ws2 + ci2 * 32;
        base[0 * 8 + u] = w0;        // even tap on x[q-1]
        base[1 * 8 + u] = w1 + w2;   // even tap on x[q]
        base[2 * 8 + u] = w0 + w1;   // odd tap on x[q]
        base[3 * 8 + u] = w2;        // odd tap on x[q+1]
    }

    u64t acc[4][4];
    #pragma unroll
    for (int j = 0; j < 4; j++)
        #pragma unroll
        for (int u = 0; u < 4; u++) acc[j][u] = 0ull;

    const int nt1 = C1 / CT;
    const int nt2 = C2Pad / CT;
    const int ntile = nt1 + nt2;

    auto stage = [&](int t, int buf) {
        if (t < nt1) {
            float* xb = xs + buf * (CT * TW1);
            int ci0 = t * CT;
            #pragma unroll
            for (int ci = 0; ci < CT; ci++) {
                const float* row = src1 + (size_t)(b * C1 + ci0 + ci) * Lin;
                unsigned sb = (unsigned)__cvta_generic_to_shared(xb + ci * TW1);
                for (int v = tid; v < NV1; v += 256) {
                    int p   = hs1 + v * 4;
                    int okb = (p >= 0 && p < Lin) ? 16 : 0;
                    int pc  = min(max(p, 0), Lin - 4);
                    cp16(sb + v * 16, row + pc, okb);
                }
            }
        } else {
            float* xb = xs + buf * (CT * TW1);
            int ci0 = (t - nt1) * CT;
            #pragma unroll
            for (int ci = 0; ci < CT; ci++) {
                int cg = ci0 + ci;
                bool cv = (cg < C2);
                const float* row = src2 + (size_t)(b * C2 + (cv ? cg : 0)) * Lin2;
                unsigned sb = (unsigned)__cvta_generic_to_shared(xb + ci * TW2);
                for (int v = tid; v < NV2; v += 256) {
                    int p   = hs2 + v * 4;
                    int okb = (cv && p >= 0 && p < Lin2) ? 16 : 0;
                    int pc  = min(max(p, 0), Lin2 - 4);
                    cp16(sb + v * 16, row + pc, okb);
                }
            }
        }
    };

    stage(0, 0);
    asm volatile("cp.async.commit_group;");

    for (int t = 0; t < ntile; t++) {
        asm volatile("cp.async.wait_group 0;");
        __syncthreads();
        if (t + 1 < ntile) {
            stage(t + 1, (t + 1) & 1);
            asm volatile("cp.async.commit_group;");
        }
        const float* xbc = xs + (t & 1) * (CT * TW1);
        if (t < nt1) {
            #pragma unroll
            for (int ci = 0; ci < CT; ci++) {
                int gci = t * CT + ci;
                const float* xr = xbc + ci * TW1 + tid * 4;
                float4 a0 = *(const float4*)xr;
                float4 a1 = *(const float4*)(xr + 4);
                float x8 = xr[8];
                float xv[9] = {a0.x, a0.y, a0.z, a0.w, a1.x, a1.y, a1.z, a1.w, x8};
                u64t xq[6];
                #pragma unroll
                for (int i = 0; i < 6; i++) PACK2(xq[i], xv[i + 3], xv[i + 3]);
                const char* wbase = (const char*)(ws3 + gci * 24);
                #pragma unroll
                for (int k = 0; k < 3; k++) {
                    ulonglong2 wa = *(const ulonglong2*)(wbase + k * 32);
                    ulonglong2 wb = *(const ulonglong2*)(wbase + k * 32 + 16);
                    #pragma unroll
                    for (int j = 0; j < 4; j++) {
                        u64t xqv = xq[j + k];
                        FMA2(acc[j][0], xqv, wa.x);
                        FMA2(acc[j][1], xqv, wa.y);
                        FMA2(acc[j][2], xqv, wb.x);
                        FMA2(acc[j][3], xqv, wb.y);
                    }
                }
            }
        } else {
            #pragma unroll
            for (int ci = 0; ci < CT; ci++) {
                int gci2 = (t - nt1) * CT + ci;
                const float* hr = xbc + ci * TW2 + tid * 2;
                float2 p0 = *(const float2*)(hr + 2);   // h[+2], h[+3]
                float2 p1 = *(const float2*)(hr + 4);   // h[+4], h[+5]
                float2 p2 = *(const float2*)(hr + 6);   // h[+6], h[+7]
                float hm = p0.y, h0 = p1.x, h1 = p1.y, h2 = p2.x;
                u64t qm, q0, q1, q2;
                PACK2(qm, hm, hm); PACK2(q0, h0, h0);
                PACK2(q1, h1, h1); PACK2(q2, h2, h2);
                const char* wbase = (const char*)(ws2 + gci2 * 32);
                ulonglong2 wA0 = *(const ulonglong2*)(wbase);        // w0
                ulonglong2 wA1 = *(const ulonglong2*)(wbase + 16);
                ulonglong2 wB0 = *(const ulonglong2*)(wbase + 32);   // w1+w2
                ulonglong2 wB1 = *(const ulonglong2*)(wbase + 48);
                ulonglong2 wC0 = *(const ulonglong2*)(wbase + 64);   // w0+w1
                ulonglong2 wC1 = *(const ulonglong2*)(wbase + 80);
                ulonglong2 wD0 = *(const ulonglong2*)(wbase + 96);   // w2
                ulonglong2 wD1 = *(const ulonglong2*)(wbase + 112);
                // j=0: even p, q=q0
                FMA2(acc[0][0], qm, wA0.x); FMA2(acc[0][1], qm, wA0.y);
                FMA2(acc[0][2], qm, wA1.x); FMA2(acc[0][3], qm, wA1.y);
                FMA2(acc[0][0], q0, wB0.x); FMA2(acc[0][1], q0, wB0.y);
                FMA2(acc[0][2], q0, wB1.x); FMA2(acc[0][3], q0, wB1.y);
                // j=1: odd p, q=q0
                FMA2(acc[1][0], q0, wC0.x); FMA2(acc[1][1], q0, wC0.y);
                FMA2(acc[1][2], q0, wC1.x); FMA2(acc[1][3], q0, wC1.y);
                FMA2(acc[1][0], q1, wD0.x); FMA2(acc[1][1], q1, wD0.y);
                FMA2(acc[1][2], q1, wD1.x); FMA2(acc[1][3], q1, wD1.y);
                // j=2: even p, q=q0+1
                FMA2(acc[2][0], q0, wA0.x); FMA2(acc[2][1], q0, wA0.y);
                FMA2(acc[2][2], q0, wA1.x); FMA2(acc[2][3], q0, wA1.y);
                FMA2(acc[2][0], q1, wB0.x); FMA2(acc[2][1], q1, wB0.y);
                FMA2(acc[2][2], q1, wB1.x); FMA2(acc[2][3], q1, wB1.y);
                // j=3: odd p, q=q0+1
                FMA2(acc[3][0], q1, wC0.x); FMA2(acc[3][1], q1, wC0.y);
                FMA2(acc[3][2], q1, wC1.x); FMA2(acc[3][3], q1, wC1.y);
                FMA2(acc[3][0], q2, wD0.x); FMA2(acc[3][1], q2, wD0.y);
                FMA2(acc[3][2], q2, wD1.x); FMA2(acc[3][3], q2, wD1.y);
            }
        }
    }

    // epilogue
    const int lid = tid & 31;
    #pragma unroll
    for (int u = 0; u < 4; u++) {
        float o0[4], o1[4];
        #pragma unroll
        for (int j = 0; j < 4; j++) UNPACK2(o0[j], o1[j], acc[j][u]);
        int c0 = co0 + 2 * u;
        float b0 = bias[c0], b1 = bias[c0 + 1];
        float s0 = 0.f, q0 = 0.f, s1 = 0.f, q1 = 0.f;
        #pragma unroll
        for (int j = 0; j < 4; j++) {
            o0[j] += b0; o1[j] += b1;
            s0 += o0[j]; q0 += o0[j] * o0[j];
            s1 += o1[j]; q1 += o1[j] * o1[j];
        }
        *(float4*)&y[((size_t)(b * Cout + c0)) * Lin + P0 + tid * 4] =
            make_float4(o0[0], o0[1], o0[2], o0[3]);
        *(float4*)&y[((size_t)(b * Cout + c0 + 1)) * Lin + P0 + tid * 4] =
            make_float4(o1[0], o1[1], o1[2], o1[3]);
        unsigned full = 0xffffffffu;
        #pragma unroll
        for (int o = 16; o > 0; o >>= 1) {
            s0 += __shfl_down_sync(full, s0, o);
            q0 += __shfl_down_sync(full, q0, o);
            s1 += __shfl_down_sync(full, s1, o);
            q1 += __shfl_down_sync(full, q1, o);
        }
        if (lid == 0) {
            atomicAdd(&redS[2 * u], s0);     atomicAdd(&redQ[2 * u], q0);
            atomicAdd(&redS[2 * u + 1], s1); atomicAdd(&redQ[2 * u + 1], q1);
        }
    }
    __syncthreads();
    if (tid < 8) {
        atomicAdd(&gsum[co0 + tid], redS[tid]);
        atomicAdd(&gsqs[co0 + tid], redQ[tid]);
    }
}

// ---------------------------------------------------------------------------
__global__ __launch_bounds__(256)
void bn_out_kernel(const float* __restrict__ raw, float* __restrict__ out,
                   int C, int L,
                   const float* __restrict__ ssum, const float* __restrict__ sqs,
                   const float* __restrict__ g, const float* __restrict__ be,
                   float invn)
{
    size_t i4 = (size_t)blockIdx.x * 256 + threadIdx.x;
    int c = (int)((i4 * 4) / (size_t)L) % C;
    float m   = ssum[c] * invn;
    float var = sqs[c] * invn - m * m;
    float sc  = g[c] * rsqrtf(var + EPSV);
    float sh  = be[c] - sc * m;
    float4 v = ((const float4*)raw)[i4];
    float4 o;
    o.x = bnl(v.x, sc, sh); o.y = bnl(v.y, sc, sh);
    o.z = bnl(v.z, sc, sh); o.w = bnl(v.w, sc, sh);
    ((float4*)out)[i4] = o;
}

// ---------------------------------------------------------------------------
// Fusion: banded correlation, BN fused into staging, channel-split, writes
// feat at HALF resolution (B, 11, 2048) via atomics.
// ---------------------------------------------------------------------------
__global__ __launch_bounds__(128)
void fusion_kernel(const float* __restrict__ f2r, float* __restrict__ feat,
                   const float* __restrict__ ssum, const float* __restrict__ sqs,
                   const float* __restrict__ gamma, const float* __restrict__ beta,
                   float invn)
{
    const int Nn = 2048, C = 256;
    const int b   = blockIdx.y;
    const int i0  = blockIdx.x * 128;
    const int cb  = blockIdx.z * 64;
    const int tid = threadIdx.x;
    const int i   = i0 + tid;
    __shared__ float tile[16][144];
    __shared__ float csc[64], csh[64];

    if (tid < 64) {
        int c = cb + tid;
        float m = ssum[c] * invn;
        float var = sqs[c] * invn - m * m;
        float sc = gamma[c] * rsqrtf(var + EPSV);
        csc[tid] = sc;
        csh[tid] = beta[c] - sc * m;
    }

    float acc[11];
    #pragma unroll
    for (int d = 0; d < 11; d++) acc[d] = 0.f;

    const bool interior = (i >= 5) && (i <= Nn - 6);

    for (int c0 = 0; c0 < 64; c0 += 16) {
        __syncthreads();
        for (int idx = tid; idx < 16 * 140; idx += 128) {
            int c = idx / 140, off = idx - c * 140;
            int p = i0 - 6 + off;
            p = min(max(p, 0), Nn - 1);
            float r = f2r[((size_t)(b * C + cb + c0 + c)) * Nn + p];
            tile[c][off] = bnl(r, csc[c0 + c], csh[c0 + c]);
        }
        __syncthreads();
        for (int c = 0; c < 16; c++) {
            float v[13];
            #pragma unroll
            for (int m = 0; m < 13; m++) v[m] = tile[c][tid + m];
            float A0 = v[5], A1 = v[6], A2 = v[7];
            if (interior) {
                #pragma unroll
                for (int dd = 0; dd < 11; dd++)
                    acc[dd] += A0 * v[dd] + A1 * v[dd + 1] + A2 * v[dd + 2];
            } else {
                for (int dd = 0; dd < 11; dd++) {
                    int j = i + dd - 5;
                    j = min(max(j, 0), Nn - 1);
                    int o0 = max(j - 1, 0) - i0 + 6;
                    int o1 = j - i0 + 6;
                    int o2 = min(j + 1, Nn - 1) - i0 + 6;
                    acc[dd] += A0 * tile[c][o0] + A1 * tile[c][o1] + A2 * tile[c][o2];
                }
            }
        }
    }
    #pragma unroll
    for (int dd = 0; dd < 11; dd++)
        atomicAdd(&feat[((size_t)(b * 11 + dd)) * 2048 + i], acc[dd]);
}

// ---------------------------------------------------------------------------
// Flow head: K=1 conv over concat(x1 raw, up(bn(d0))); twin positions share
// d0 loads; BN-stat reduction fused into epilogue.
// ---------------------------------------------------------------------------
__global__ __launch_bounds__(256)
void flow_conv_kernel(const float* __restrict__ x1, const float* __restrict__ d0,
                      const float* __restrict__ w, const float* __restrict__ bias,
                      const float* __restrict__ ssum, const float* __restrict__ sqs,
                      const float* __restrict__ gamma, const float* __restrict__ beta,
                      float invn,
                      float* __restrict__ out,
                      float* __restrict__ osum, float* __restrict__ osqs)
{
    const int Nn = 16384;
    __shared__ float csc[128], csh[128];
    __shared__ float redS[2], redQ[2];
    int tid = threadIdx.x;
    if (tid < 128) {
        float m = ssum[tid] * invn;
        float var = sqs[tid] * invn - m * m;
        float sc = gamma[tid] * rsqrtf(var + EPSV);
        csc[tid] = sc;
        csh[tid] = beta[tid] - sc * m;
    }
    if (tid < 2) { redS[tid] = 0.f; redQ[tid] = 0.f; }
    __syncthreads();

    int b = blockIdx.y;
    int i = blockIdx.x * 256 + tid;
    float2 xv = ((const float2*)&x1[(size_t)b * Nn])[i];
    float a00 = w[0] * xv.x, a01 = w[0] * xv.y;
    float a10 = w[129] * xv.x, a11 = w[129] * xv.y;
    const float* dp = d0 + (size_t)b * 128 * 8192 + i;
    #pragma unroll 4
    for (int ci = 0; ci < 128; ci++) {
        float r = dp[(size_t)ci * 8192];
        float v = bnl(r, csc[ci], csh[ci]);
        a00 += w[1 + ci] * v;   a01 += w[1 + ci] * v;
        a10 += w[130 + ci] * v; a11 += w[130 + ci] * v;
    }
    float v00 = a00 + bias[0], v01 = a01 + bias[0];
    float v10 = a10 + bias[1], v11 = a11 + bias[1];
    ((float2*)&out[((size_t)(b * 2 + 0)) * Nn])[i] = make_float2(v00, v01);
    ((float2*)&out[((size_t)(b * 2 + 1)) * Nn])[i] = make_float2(v10, v11);

    float s0 = v00 + v01, q0 = v00 * v00 + v01 * v01;
    float s1 = v10 + v11, q1 = v10 * v10 + v11 * v11;
    unsigned full = 0xffffffffu;
    #pragma unroll
    for (int o = 16; o > 0; o >>= 1) {
        s0 += __shfl_down_sync(full, s0, o);
        q0 += __shfl_down_sync(full, q0, o);
        s1 += __shfl_down_sync(full, s1, o);
        q1 += __shfl_down_sync(full, q1, o);
    }
    if ((tid & 31) == 0) {
        atomicAdd(&redS[0], s0); atomicAdd(&redQ[0], q0);
        atomicAdd(&redS[1], s1); atomicAdd(&redQ[1], q1);
    }
    __syncthreads();
    if (tid < 2) {
        atomicAdd(&osum[tid], redS[tid]);
        atomicAdd(&osqs[tid], redQ[tid]);
    }
}

// ---------------------------------------------------------------------------
__global__ __launch_bounds__(256)
void flow_apply_kernel(const float* __restrict__ fl,
                       const float* __restrict__ ssum, const float* __restrict__ sqs,
                       const float* __restrict__ gamma, const float* __restrict__ beta,
                       float* __restrict__ out, float invn)
{
    const int Nn = 16384;
    int b = blockIdx.y;
    int p = blockIdx.x * 256 + threadIdx.x;
    float m0 = ssum[0] * invn, m1 = ssum[1] * invn;
    float v0 = sqs[0] * invn - m0 * m0;
    float v1 = sqs[1] * invn - m1 * m1;
    float sc0 = gamma[0] * rsqrtf(v0 + EPSV), sh0 = beta[0] - sc0 * m0;
    float sc1 = gamma[1] * rsqrtf(v1 + EPSV), sh1 = beta[1] - sc1 * m1;
    float a = fl[((size_t)(b * 2 + 0)) * Nn + p];
    float c = fl[((size_t)(b * 2 + 1)) * Nn + p];
    float2 r;
    r.x = bnl(a, sc0, sh0);
    r.y = bnl(c, sc1, sh1);
    ((float2*)out)[(size_t)b * Nn + p] = r;
}

// ---------------------------------------------------------------------------
extern "C" void kernel_launch(void* const* d_in, const int* in_sizes, int n_in,
                              void* d_out, int out_size)
{
    (void)in_sizes; (void)n_in; (void)out_size;
    const float* scan1 = (const float*)d_in[0];
    const float* e0w = (const float*)d_in[1];
    const float* e0b = (const float*)d_in[2];
    const float* e0g = (const float*)d_in[3];
    const float* e0e = (const float*)d_in[4];
    const float* e1w = (const float*)d_in[5];
    const float* e1b = (const float*)d_in[6];
    const float* e1g = (const float*)d_in[7];
    const float* e1e = (const float*)d_in[8];
    const float* e2w = (const float*)d_in[9];
    const float* e2b = (const float*)d_in[10];
    const float* e2g = (const float*)d_in[11];
    const float* e2e = (const float*)d_in[12];
    const float* d1w = (const float*)d_in[13];
    const float* d1b = (const float*)d_in[14];
    const float* d1g = (const float*)d_in[15];
    const float* d1e = (const float*)d_in[16];
    const float* d0w = (const float*)d_in[17];
    const float* d0b = (const float*)d_in[18];
    const float* d0g = (const float*)d_in[19];
    const float* d0e = (const float*)d_in[20];
    const float* fw  = (const float*)d_in[21];
    const float* fb  = (const float*)d_in[22];
    const float* fg  = (const float*)d_in[23];
    const float* fe  = (const float*)d_in[24];

    float* base = nullptr;
    cudaGetSymbolAddress((void**)&base, g_scratch);
    float* f0r  = base + OFF_F0R;
    float* t0   = base + OFF_T0;
    float* f1r  = base + OFF_F1R;
    float* t1   = base + OFF_T1;
    float* f2r  = base + OFF_F2R;
    float* feat = base + OFF_FEAT;
    float* d1r  = base + OFF_D1R;
    float* td1  = base + OFF_TD1;
    float* d0r  = base + OFF_D0R;
    float* fl   = base + OFF_FL;
    float* sum  = base + OFF_SUM;
    float* sqs  = base + OFF_SQS;

    const float i0n = 1.f / (8.f * 8192.f);
    const float i1n = 1.f / (8.f * 4096.f);
    const float i2n = 1.f / (8.f * 2048.f);

    // smem sizes (bytes)
    const int SM_E0 = (1 * 24 + 2 * 1 * 2056) * 4;                 // 16544
    const int SM_E1 = (64 * 24 + 2 * 2 * 2056) * 4;                // 39040
    const int SM_E2 = (128 * 24 + 2 * 2 * 2056) * 4;               // 45184
    const int SM_D1 = (128 * 24 + 12 * 32 + 2 * 4 * 1032) * 4;     // 46848
    const int SM_D0 = (64 * 24 + 128 * 32 + 2 * 4 * 1032) * 4;     // 55552
    cudaFuncSetAttribute(conv3_cp<2, 1>, cudaFuncAttributeMaxDynamicSharedMemorySize, SM_E0);
    cudaFuncSetAttribute(conv3_cp<2, 2>, cudaFuncAttributeMaxDynamicSharedMemorySize, SM_E2);
    cudaFuncSetAttribute(conv3_mix<4>, cudaFuncAttributeMaxDynamicSharedMemorySize, SM_D0);

    zero_kernel<<<6, 256>>>(sum, 1412);
    zero_kernel<<<704, 256>>>(feat, 180224);

    // enc0
    conv3_cp<2, 1><<<dim3(8, 8, 8), 256, SM_E0>>>(
        scan1, 1, 16384, 8192, 1, 1, e0w, e0b, f0r, sum + 0, sqs + 0);
    bn_out_kernel<<<4096, 256>>>(f0r, t0, 64, 8192, sum + 0, sqs + 0, e0g, e0e, i0n);

    // enc1
    conv3_cp<2, 2><<<dim3(4, 16, 8), 256, SM_E1>>>(
        t0, 64, 8192, 4096, 64, 64, e1w, e1b, f1r, sum + 64, sqs + 64);
    bn_out_kernel<<<4096, 256>>>(f1r, t1, 128, 4096, sum + 64, sqs + 64, e1g, e1e, i1n);

    // enc2
    conv3_cp<2, 2><<<dim3(2, 32, 8), 256, SM_E2>>>(
        t1, 128, 4096, 2048, 128, 128, e2w, e2b, f2r, sum + 192, sqs + 192);

    // fusion -> feat (half-res)
    fusion_kernel<<<dim3(16, 8, 4), 128>>>(f2r, feat,
                                           sum + 192, sqs + 192, e2g, e2e, i2n);

    // dec1: src1 = t1 (128, full 4096), src2 = feat (11, half 2048)
    conv3_mix<4><<<dim3(4, 16, 8), 256, SM_D1>>>(
        t1, 128, feat, 11, 12, 4096, 128,
        d1w, d1b, d1r, sum + 448, sqs + 448);
    bn_out_kernel<<<4096, 256>>>(d1r, td1, 128, 4096, sum + 448, sqs + 448, d1g, d1e, i1n);

    // dec0: src1 = t0 (64, full 8192), src2 = td1 (128, half 4096)
    conv3_mix<4><<<dim3(8, 16, 8), 256, SM_D0>>>(
        t0, 64, td1, 128, 128, 8192, 128,
        d0w, d0b, d0r, sum + 576, sqs + 576);

    // flow head (stats fused)
    flow_conv_kernel<<<dim3(32, 8), 256>>>(scan1, d0r, fw, fb,
                                           sum + 576, sqs + 576, d0g, d0e, i0n,
                                           fl, sum + 704, sqs + 704);
    flow_apply_kernel<<<dim3(64, 8), 256>>>(fl, sum + 704, sqs + 704, fg, fe,
                                            (float*)d_out, 1.f / (8.f * 16384.f));
}